// round 1
// baseline (speedup 1.0000x reference)
#include <cuda_runtime.h>
#include <cstdint>

#define Hh 128
#define Ww 128
#define Cc 64
#define Oo 64
#define KK 9
#define Bb 4

// Scratch (no allocations allowed): NHWC image + transposed weights.
__device__ float g_xt[(size_t)Bb * Hh * Ww * Cc];   // [b][y][x][c]
__device__ float g_wt[KK * Cc * Oo];                // [t][c][o]

// ---------------------------------------------------------------------------
// x: [b][c][y][x] -> g_xt: [b][y][x][c]   (one block per (b,y) row)
// ---------------------------------------------------------------------------
__global__ __launch_bounds__(256) void transpose_x_kernel(const float* __restrict__ x) {
    __shared__ float tile[64][129];
    int by = blockIdx.x;                 // b*128 + y
    int b = by >> 7, y = by & 127;
    const float* src = x + (size_t)b * Cc * Hh * Ww + (size_t)y * Ww;
    for (int i = threadIdx.x; i < Cc * Ww; i += 256) {
        int c = i >> 7, xx = i & 127;
        tile[c][xx] = src[(size_t)c * Hh * Ww + xx];      // coalesced read
    }
    __syncthreads();
    float* dst = g_xt + (size_t)by * Ww * Cc;
    for (int i = threadIdx.x; i < Cc * Ww; i += 256) {
        int xx = i >> 6, c = i & 63;
        dst[i] = tile[c][xx];                             // coalesced write
    }
}

// ---------------------------------------------------------------------------
// weight: [o][c][t] -> g_wt: [t][c][o]
// ---------------------------------------------------------------------------
__global__ void transpose_w_kernel(const float* __restrict__ w) {
    int i = blockIdx.x * blockDim.x + threadIdx.x;
    if (i < KK * Cc * Oo) {
        int t = i / (Cc * Oo);
        int r = i - t * (Cc * Oo);
        int c = r >> 6, o = r & 63;
        g_wt[i] = w[(o * Cc + c) * KK + t];
    }
}

// packed f32x2 FMA (Blackwell): d = a*b + d elementwise on two f32 lanes
#define FMA2(d, a, b) asm("fma.rn.f32x2 %0, %1, %2, %0;" : "+l"(d) : "l"(a), "l"(b))

// ---------------------------------------------------------------------------
// Main kernel. Block = one (b,y) row of 128 pixels, 256 threads.
// thread = (px = tid&127, o-half = tid>>7), 32 outputs in 16 f32x2 registers.
// Per tap: [setup coords | stage weight tile] -> cooperative gather s[c][px]
// -> broadcast-weight FMA2 accumulation.
// ---------------------------------------------------------------------------
__global__ __launch_bounds__(256) void deform_main(
    const float* __restrict__ offset,
    const float* __restrict__ bias,
    float* __restrict__ out)
{
    extern __shared__ float smem[];
    float* s_s  = smem;                 // sampled values [64][129] (padded)
    float* s_w  = smem + 64 * 129;      // weight tile for current tap [c][o]
    float* s_w4 = s_w + 64 * 64;        // bilinear weights [128][4]
    int*   s_ix = (int*)(s_w4 + 128 * 4); // corner indices  [128][4]

    const int tid = threadIdx.x;
    const int bid = blockIdx.x;
    const int b = bid >> 7, y = bid & 127;

    const float* xb   = g_xt + (size_t)b * Hh * Ww * Cc;
    const float* offb = offset + (size_t)b * (2 * KK) * Hh * Ww + (size_t)y * Ww;

    unsigned long long acc[16];
#pragma unroll
    for (int i = 0; i < 16; ++i) acc[i] = 0ull;

    const int px = tid & 127;
    const int oh = tid >> 7;            // 0 or 1 (o-half)

    for (int t = 0; t < KK; ++t) {
        __syncthreads();                // protect smem from previous phase
        if (tid < 128) {
            // --- per-pixel bilinear setup for tap t ---
            int xx = tid;
            float ox = offb[(size_t)(2 * t)     * Hh * Ww + xx];
            float oy = offb[(size_t)(2 * t + 1) * Hh * Ww + xx];
            float pxf = (float)xx + ox;
            float pyf = (float)y  + oy;
            float x0f = floorf(pxf), y0f = floorf(pyf);
            float fx = pxf - x0f, fy = pyf - y0f;
            int x0 = (int)x0f, y0 = (int)y0f;
            int x1 = x0 + 1,   y1 = y0 + 1;
            float vx0 = (x0 >= 0 && x0 < Ww) ? 1.f : 0.f;
            float vx1 = (x1 >= 0 && x1 < Ww) ? 1.f : 0.f;
            float vy0 = (y0 >= 0 && y0 < Hh) ? 1.f : 0.f;
            float vy1 = (y1 >= 0 && y1 < Hh) ? 1.f : 0.f;
            int cx0 = min(max(x0, 0), Ww - 1), cx1 = min(max(x1, 0), Ww - 1);
            int cy0 = min(max(y0, 0), Hh - 1), cy1 = min(max(y1, 0), Hh - 1);
            s_w4[xx * 4 + 0] = (1.f - fx) * (1.f - fy) * vx0 * vy0;
            s_w4[xx * 4 + 1] = fx * (1.f - fy) * vx1 * vy0;
            s_w4[xx * 4 + 2] = (1.f - fx) * fy * vx0 * vy1;
            s_w4[xx * 4 + 3] = fx * fy * vx1 * vy1;
            s_ix[xx * 4 + 0] = cy0 * Ww + cx0;
            s_ix[xx * 4 + 1] = cy0 * Ww + cx1;
            s_ix[xx * 4 + 2] = cy1 * Ww + cx0;
            s_ix[xx * 4 + 3] = cy1 * Ww + cx1;
        } else {
            // --- stage weight tile for tap t: 4096 floats via float4 ---
            const float4* wsrc = (const float4*)(g_wt + (size_t)t * Cc * Oo);
            float4* wdst = (float4*)s_w;
            int l = tid - 128;
#pragma unroll
            for (int i = 0; i < 8; ++i) wdst[l + i * 128] = wsrc[l + i * 128];
        }
        __syncthreads();

        // --- cooperative gather: warp lanes = 2 pixels x 16 channel-groups ---
        // each (pixel,corner) read is 16 contiguous float4 -> 2 cache lines.
#pragma unroll
        for (int iter = 0; iter < 8; ++iter) {
            int task = tid + iter * 256;       // 0..2047 = 128 px * 16 cg
            int gpx = task >> 4, cg = task & 15;
            float w0 = s_w4[gpx * 4 + 0], w1 = s_w4[gpx * 4 + 1];
            float w2 = s_w4[gpx * 4 + 2], w3 = s_w4[gpx * 4 + 3];
            int i0 = s_ix[gpx * 4 + 0], i1 = s_ix[gpx * 4 + 1];
            int i2 = s_ix[gpx * 4 + 2], i3 = s_ix[gpx * 4 + 3];
            float4 v0 = *((const float4*)(xb + ((size_t)i0 << 6)) + cg);
            float4 v1 = *((const float4*)(xb + ((size_t)i1 << 6)) + cg);
            float4 v2 = *((const float4*)(xb + ((size_t)i2 << 6)) + cg);
            float4 v3 = *((const float4*)(xb + ((size_t)i3 << 6)) + cg);
            float s0 = fmaf(w3, v3.x, fmaf(w2, v2.x, fmaf(w1, v1.x, w0 * v0.x)));
            float s1 = fmaf(w3, v3.y, fmaf(w2, v2.y, fmaf(w1, v1.y, w0 * v0.y)));
            float s2 = fmaf(w3, v3.z, fmaf(w2, v2.z, fmaf(w1, v1.z, w0 * v0.z)));
            float s3 = fmaf(w3, v3.w, fmaf(w2, v2.w, fmaf(w1, v1.w, w0 * v0.w)));
            int crow = cg * 4;
            s_s[(crow + 0) * 129 + gpx] = s0;
            s_s[(crow + 1) * 129 + gpx] = s1;
            s_s[(crow + 2) * 129 + gpx] = s2;
            s_s[(crow + 3) * 129 + gpx] = s3;
        }
        __syncthreads();

        // --- accumulate: for each channel, broadcast weights + 16 FMA2 ---
        const float* swo = s_w + oh * 32;
#pragma unroll 2
        for (int c = 0; c < 64; ++c) {
            float sf = s_s[c * 129 + px];           // conflict-free (stride 1)
            unsigned long long sv;
            asm("mov.b64 %0, {%1, %1};" : "=l"(sv) : "r"(__float_as_uint(sf)));
            const ulonglong2* wp = (const ulonglong2*)(swo + c * 64);
#pragma unroll
            for (int j = 0; j < 8; ++j) {
                ulonglong2 wv = wp[j];              // LDS.128 broadcast
                FMA2(acc[2 * j],     wv.x, sv);     // outputs 4j, 4j+1
                FMA2(acc[2 * j + 1], wv.y, sv);     // outputs 4j+2, 4j+3
            }
        }
    }

    // --- epilogue: out[b][o][y][px] = acc + bias[o], coalesced over px ---
    float* op = out + ((size_t)b * Oo * Hh + y) * Ww + px;
#pragma unroll
    for (int j = 0; j < 16; ++j) {
        int o = oh * 32 + 2 * j;
        float lo = __uint_as_float((unsigned)(acc[j] & 0xffffffffull));
        float hi = __uint_as_float((unsigned)(acc[j] >> 32));
        op[(size_t)o * Hh * Ww]       = lo + bias[o];
        op[(size_t)(o + 1) * Hh * Ww] = hi + bias[o + 1];
    }
}

extern "C" void kernel_launch(void* const* d_in, const int* in_sizes, int n_in,
                              void* d_out, int out_size) {
    const float* x      = (const float*)d_in[0];
    const float* offset = (const float*)d_in[1];
    const float* weight = (const float*)d_in[2];
    const float* bias   = (const float*)d_in[3];
    float* out = (float*)d_out;

    transpose_x_kernel<<<Bb * Hh, 256>>>(x);
    transpose_w_kernel<<<(KK * Cc * Oo + 255) / 256, 256>>>(weight);

    // smem: s_s 64*129 + s_w 64*64 + s_w4 128*4 floats + s_ix 128*4 ints
    const int smem_bytes = (64 * 129 + 64 * 64 + 128 * 4) * 4 + 128 * 4 * 4;
    cudaFuncSetAttribute(deform_main, cudaFuncAttributeMaxDynamicSharedMemorySize,
                         smem_bytes);
    deform_main<<<Bb * Hh, 256, smem_bytes>>>(offset, bias, out);
}

// round 2
// speedup vs baseline: 1.3633x; 1.3633x over previous
#include <cuda_runtime.h>
#include <cstdint>

#define Hh 128
#define Ww 128
#define Cc 64
#define Oo 64
#define KK 9
#define Bb 4
#define HW (Hh * Ww)

#define SPAD 130                 // s tile row stride (floats), even for LDS.64
#define OSTRIDE 132              // epilogue staging stride (16B-aligned rows)

// Scratch (no allocations allowed): NHWC image + transposed weights.
__device__ float g_xt[(size_t)Bb * Hh * Ww * Cc];   // [b][y][x][c]
__device__ float g_wt[KK * Cc * Oo];                // [t][c][o]

// ---------------------------------------------------------------------------
// x: [b][c][y][x] -> g_xt: [b][y][x][c]   (one block per (b,y) row)
// ---------------------------------------------------------------------------
__global__ __launch_bounds__(256) void transpose_x_kernel(const float* __restrict__ x) {
    __shared__ float tile[64][129];
    int by = blockIdx.x;                 // b*128 + y
    int b = by >> 7, y = by & 127;
    const float* src = x + (size_t)b * Cc * HW + (size_t)y * Ww;
    for (int i = threadIdx.x; i < Cc * Ww; i += 256) {
        int c = i >> 7, xx = i & 127;
        tile[c][xx] = src[(size_t)c * HW + xx];           // coalesced read
    }
    __syncthreads();
    float4* dst4 = (float4*)(g_xt + (size_t)by * Ww * Cc);
    for (int i = threadIdx.x; i < Cc * Ww / 4; i += 256) {
        int xx = i >> 4, q = i & 15;                      // 16 float4 per pixel
        int c = q * 4;
        dst4[i] = make_float4(tile[c][xx], tile[c + 1][xx],
                              tile[c + 2][xx], tile[c + 3][xx]);
    }
}

// ---------------------------------------------------------------------------
// weight: [o][c][t] -> g_wt: [t][c][o]
// ---------------------------------------------------------------------------
__global__ void transpose_w_kernel(const float* __restrict__ w) {
    int i = blockIdx.x * blockDim.x + threadIdx.x;
    if (i < KK * Cc * Oo) {
        int t = i / (Cc * Oo);
        int r = i - t * (Cc * Oo);
        int c = r >> 6, o = r & 63;
        g_wt[i] = w[(o * Cc + c) * KK + t];
    }
}

// packed f32x2 FMA (Blackwell): d = a*b + d elementwise on two f32 lanes
#define FMA2(d, a, b) asm("fma.rn.f32x2 %0, %1, %2, %0;" : "+l"(d) : "l"(a), "l"(b))

// ---------------------------------------------------------------------------
// Main kernel: warp-specialized pipeline. Block = one (b,y) row, 384 threads.
//   tid <  256 : consumers. thread = (px0 = (tid&31)*4, o0 = (tid>>5)*8).
//                32 outputs in 16 f32x2 (o-pair packed) registers.
//   tid >= 256 : producers (128 threads). For tap t+1: bilinear coords,
//                cooperative gather + combine into s tile, weight staging.
// Double-buffered s/w tiles, one __syncthreads per tap.
// ---------------------------------------------------------------------------
__global__ __launch_bounds__(384, 2) void deform_main(
    const float* __restrict__ offset,
    const float* __restrict__ bias,
    float* __restrict__ out)
{
    extern __shared__ float smem[];
    float* sms  = smem;                        // 2 x [64][SPAD] sampled tiles
    float* smw  = smem + 2 * 64 * SPAD;        // 2 x [64][64] weight tiles
    float* smw4 = smw + 2 * 64 * 64;           // bilinear weights [128][4]
    int*   smix = (int*)(smw4 + 128 * 4);      // corner indices  [128][4]

    const int tid = threadIdx.x;
    const int bid = blockIdx.x;
    const int b = bid >> 7, y = bid & 127;

    const float* xb   = g_xt + (size_t)b * HW * Cc;
    const float* offb = offset + (size_t)b * (2 * KK) * HW + (size_t)y * Ww;

    const bool producer = (tid >= 256);
    const int ptid = tid - 256;

    // consumer identity
    const int px0 = (tid & 31) * 4;
    const int o0  = (tid >> 5) * 8;

    unsigned long long acc[16];                // acc[i*4+k]: px0+i, o-pair k
#pragma unroll
    for (int i = 0; i < 16; ++i) acc[i] = 0ull;

    // ---------------- producer routine for tap tt ----------------
    auto produce = [&](int tt) {
        float* sdst = sms + (tt & 1) * 64 * SPAD;
        // coords for all 128 pixels (1 per producer thread)
        {
            int xx = ptid;
            float ox = offb[(size_t)(2 * tt)     * HW + xx];
            float oy = offb[(size_t)(2 * tt + 1) * HW + xx];
            float pxf = (float)xx + ox;
            float pyf = (float)y  + oy;
            float x0f = floorf(pxf), y0f = floorf(pyf);
            float fx = pxf - x0f, fy = pyf - y0f;
            int x0 = (int)x0f, y0 = (int)y0f;
            int x1 = x0 + 1,   y1 = y0 + 1;
            float vx0 = (x0 >= 0 && x0 < Ww) ? 1.f : 0.f;
            float vx1 = (x1 >= 0 && x1 < Ww) ? 1.f : 0.f;
            float vy0 = (y0 >= 0 && y0 < Hh) ? 1.f : 0.f;
            float vy1 = (y1 >= 0 && y1 < Hh) ? 1.f : 0.f;
            int cx0 = min(max(x0, 0), Ww - 1), cx1 = min(max(x1, 0), Ww - 1);
            int cy0 = min(max(y0, 0), Hh - 1), cy1 = min(max(y1, 0), Hh - 1);
            smw4[xx * 4 + 0] = (1.f - fx) * (1.f - fy) * vx0 * vy0;
            smw4[xx * 4 + 1] = fx * (1.f - fy) * vx1 * vy0;
            smw4[xx * 4 + 2] = (1.f - fx) * fy * vx0 * vy1;
            smw4[xx * 4 + 3] = fx * fy * vx1 * vy1;
            smix[xx * 4 + 0] = cy0 * Ww + cx0;
            smix[xx * 4 + 1] = cy0 * Ww + cx1;
            smix[xx * 4 + 2] = cy1 * Ww + cx0;
            smix[xx * 4 + 3] = cy1 * Ww + cx1;
        }
        // stage weight tile (4096 floats) — independent of coords
        {
            const float4* wsrc = (const float4*)(g_wt + (size_t)tt * Cc * Oo);
            float4* wdst = (float4*)(smw + (tt & 1) * 64 * 64);
#pragma unroll
            for (int i = 0; i < 8; ++i) wdst[ptid + i * 128] = wsrc[ptid + i * 128];
        }
        asm volatile("bar.sync 1, 128;" ::: "memory");   // producers only
        // cooperative gather: 2048 tasks = 128 px * 16 channel-groups
#pragma unroll 4
        for (int it = 0; it < 16; ++it) {
            int task = it * 128 + ptid;
            int gpx = task >> 4, cg = task & 15;
            float w0 = smw4[gpx * 4 + 0], w1 = smw4[gpx * 4 + 1];
            float w2 = smw4[gpx * 4 + 2], w3 = smw4[gpx * 4 + 3];
            int i0 = smix[gpx * 4 + 0], i1 = smix[gpx * 4 + 1];
            int i2 = smix[gpx * 4 + 2], i3 = smix[gpx * 4 + 3];
            float4 v0 = *((const float4*)(xb + ((size_t)i0 << 6)) + cg);
            float4 v1 = *((const float4*)(xb + ((size_t)i1 << 6)) + cg);
            float4 v2 = *((const float4*)(xb + ((size_t)i2 << 6)) + cg);
            float4 v3 = *((const float4*)(xb + ((size_t)i3 << 6)) + cg);
            float s0 = fmaf(w3, v3.x, fmaf(w2, v2.x, fmaf(w1, v1.x, w0 * v0.x)));
            float s1 = fmaf(w3, v3.y, fmaf(w2, v2.y, fmaf(w1, v1.y, w0 * v0.y)));
            float s2 = fmaf(w3, v3.z, fmaf(w2, v2.z, fmaf(w1, v1.z, w0 * v0.z)));
            float s3 = fmaf(w3, v3.w, fmaf(w2, v2.w, fmaf(w1, v1.w, w0 * v0.w)));
            float* dc = sdst + (cg * 4) * SPAD + gpx;
            dc[0 * SPAD] = s0;
            dc[1 * SPAD] = s1;
            dc[2 * SPAD] = s2;
            dc[3 * SPAD] = s3;
        }
    };

    // ---------------- pipeline ----------------
    if (producer) produce(0);
    __syncthreads();

    for (int t = 0; t < KK; ++t) {
        if (producer) {
            if (t + 1 < KK) produce(t + 1);
        } else {
            const float* sb = sms + (t & 1) * 64 * SPAD + px0;
            const float* sw = smw + (t & 1) * 64 * 64 + o0;
#pragma unroll 2
            for (int c = 0; c < 64; ++c) {
                unsigned long long p01 = *(const unsigned long long*)(sb + c * SPAD);
                unsigned long long p23 = *(const unsigned long long*)(sb + c * SPAD + 2);
                ulonglong2 wA = *(const ulonglong2*)(sw + c * 64);      // pairs 0,1
                ulonglong2 wB = *(const ulonglong2*)(sw + c * 64 + 4);  // pairs 2,3
                unsigned s0, s1, s2, s3;
                asm("mov.b64 {%0,%1}, %2;" : "=r"(s0), "=r"(s1) : "l"(p01));
                asm("mov.b64 {%0,%1}, %2;" : "=r"(s2), "=r"(s3) : "l"(p23));
                unsigned long long d0, d1, d2, d3;
                asm("mov.b64 %0, {%1,%1};" : "=l"(d0) : "r"(s0));
                asm("mov.b64 %0, {%1,%1};" : "=l"(d1) : "r"(s1));
                asm("mov.b64 %0, {%1,%1};" : "=l"(d2) : "r"(s2));
                asm("mov.b64 %0, {%1,%1};" : "=l"(d3) : "r"(s3));
                FMA2(acc[0],  wA.x, d0); FMA2(acc[1],  wA.y, d0);
                FMA2(acc[2],  wB.x, d0); FMA2(acc[3],  wB.y, d0);
                FMA2(acc[4],  wA.x, d1); FMA2(acc[5],  wA.y, d1);
                FMA2(acc[6],  wB.x, d1); FMA2(acc[7],  wB.y, d1);
                FMA2(acc[8],  wA.x, d2); FMA2(acc[9],  wA.y, d2);
                FMA2(acc[10], wB.x, d2); FMA2(acc[11], wB.y, d2);
                FMA2(acc[12], wA.x, d3); FMA2(acc[13], wA.y, d3);
                FMA2(acc[14], wB.x, d3); FMA2(acc[15], wB.y, d3);
            }
        }
        __syncthreads();
    }

    // ---------------- epilogue: stage -> coalesced store ----------------
    if (!producer) {
        float* stg = sms;                        // reuse, stride OSTRIDE
#pragma unroll
        for (int k = 0; k < 4; ++k) {
            float blo = bias[o0 + 2 * k];
            float bhi = bias[o0 + 2 * k + 1];
#pragma unroll
            for (int i = 0; i < 4; ++i) {
                unsigned long long a = acc[i * 4 + k];
                float lo = __uint_as_float((unsigned)(a & 0xffffffffull));
                float hi = __uint_as_float((unsigned)(a >> 32));
                stg[(o0 + 2 * k) * OSTRIDE + px0 + i]     = lo + blo;
                stg[(o0 + 2 * k + 1) * OSTRIDE + px0 + i] = hi + bhi;
            }
        }
    }
    __syncthreads();

    {
        float* outb = out + ((size_t)b * Oo * Hh + y) * Ww;   // + o*HW + x
        const float* stg = sms;
        for (int idx = tid; idx < Oo * Ww / 4; idx += 384) {
            int o = idx >> 5, q = idx & 31;
            float4 v = *(const float4*)(stg + o * OSTRIDE + q * 4);
            *(float4*)(outb + (size_t)o * HW + q * 4) = v;
        }
    }
}

extern "C" void kernel_launch(void* const* d_in, const int* in_sizes, int n_in,
                              void* d_out, int out_size) {
    const float* x      = (const float*)d_in[0];
    const float* offset = (const float*)d_in[1];
    const float* weight = (const float*)d_in[2];
    const float* bias   = (const float*)d_in[3];
    float* out = (float*)d_out;

    transpose_x_kernel<<<Bb * Hh, 256>>>(x);
    transpose_w_kernel<<<(KK * Cc * Oo + 255) / 256, 256>>>(weight);

    // smem: 2*64*SPAD + 2*64*64 + 128*4 floats + 128*4 ints
    const int smem_bytes = (2 * 64 * SPAD + 2 * 64 * 64 + 128 * 4 + 128 * 4) * 4;
    cudaFuncSetAttribute(deform_main, cudaFuncAttributeMaxDynamicSharedMemorySize,
                         smem_bytes);
    deform_main<<<Bb * Hh, 384, smem_bytes>>>(offset, bias, out);
}

// round 4
// speedup vs baseline: 2.2455x; 1.6471x over previous
#include <cuda_runtime.h>
#include <cstdint>

#define Hh 128
#define Ww 128
#define Cc 64
#define Oo 64
#define KK 9
#define Bb 4
#define HW (Hh * Ww)

#define SPAD 130                 // fallback s tile row stride
#define OSTRIDE 132              // fallback epilogue staging stride

// ---------------- scratch (no allocs allowed) ----------------
__device__ float g_xt[(size_t)Bb * HW * Cc];        // NHWC image [b][y][x][c]
__device__ float g_wt[KK * Cc * Oo];                // fallback: [t][c][o]
__device__ float g_wt_hi[KK * 4096];                // tcgen05: per-tap B tile [o][c] tf32-hi (pre-swizzled)
__device__ float g_wt_lo[KK * 4096];                // tcgen05: tf32-lo residual

// Is the current device-compile pass feature-complete sm_103a?
#if defined(__CUDA_ARCH__) && (defined(__CUDA_ARCH_FEAT_SM103_ALL) || defined(__CUDA_ARCH_FEAT_SM100_ALL))
#define HAS_TCGEN05 1
#else
#define HAS_TCGEN05 0
#endif

__device__ __forceinline__ float tf32_rna(float x) {
    // cvt.rna.tf32 is plain sm_90+; safe on all passes
    uint32_t u; asm("cvt.rna.tf32.f32 %0, %1;" : "=r"(u) : "f"(x));
    return __uint_as_float(u);
}
__device__ __forceinline__ uint32_t sw128(uint32_t off) { return off ^ ((off >> 3) & 0x70); }

// ---------------------------------------------------------------------------
// x: [b][c][y][x] -> g_xt: [b][y][x][c]. 2048 blocks x 128 thr, tile 32c x 128x
// ---------------------------------------------------------------------------
__global__ __launch_bounds__(128) void transpose_x_kernel(const float* __restrict__ x) {
    __shared__ float tile[32][129];
    int blk = blockIdx.x;                // b*256 + y*2 + half
    int b = blk >> 8;
    int rem = blk & 255;
    int y = rem >> 1;
    int c0 = (rem & 1) * 32;
    const float* src = x + ((size_t)(b * Cc + c0)) * HW + (size_t)y * Ww;
    int t = threadIdx.x;
#pragma unroll
    for (int k = 0; k < 8; ++k) {
        int i = t + k * 128;             // 32 c * 32 x4-groups
        int c = i >> 5, x4 = i & 31;
        float4 v = *(const float4*)(src + (size_t)c * HW + x4 * 4);
        tile[c][x4 * 4 + 0] = v.x; tile[c][x4 * 4 + 1] = v.y;
        tile[c][x4 * 4 + 2] = v.z; tile[c][x4 * 4 + 3] = v.w;
    }
    __syncthreads();
    float* dst = g_xt + ((size_t)(b * Hh + y) * Ww) * Cc + c0;
#pragma unroll
    for (int k = 0; k < 8; ++k) {
        int i = t + k * 128;             // 128 x * 8 c4-groups
        int xx = i >> 3, c4 = i & 7;
        float4 v = make_float4(tile[c4 * 4 + 0][xx], tile[c4 * 4 + 1][xx],
                               tile[c4 * 4 + 2][xx], tile[c4 * 4 + 3][xx]);
        *(float4*)(dst + (size_t)xx * Cc + c4 * 4) = v;
    }
}

// ---------------------------------------------------------------------------
// weight prep: fallback [t][c][o] AND tcgen05 hi/lo blocked-SW128 tiles.
// ---------------------------------------------------------------------------
__global__ void prep_w_kernel(const float* __restrict__ w) {
    int i = blockIdx.x * blockDim.x + threadIdx.x;
    if (i >= KK * 4096) return;
    int t = i >> 12, r = i & 4095;
    int o = r >> 6, c = r & 63;
    float val = w[(o * Cc + c) * KK + t];
    g_wt[t * 4096 + c * 64 + o] = val;                 // fallback layout
    float hi = tf32_rna(val);
    float lo = val - hi;
    // B tile [o=64 rows][c=64 tf32]: atom 8 rows x 128B, atom_off=(o>>3)+(c>>5)*8
    uint32_t off = (uint32_t)(((o >> 3) + (c >> 5) * 8) * 1024 + (o & 7) * 128 + (c & 31) * 4);
    uint32_t sw = sw128(off) >> 2;
    g_wt_hi[t * 4096 + sw] = hi;
    g_wt_lo[t * 4096 + sw] = lo;
}

// packed f32x2 FMA: d = a*b + d
#define FMA2(d, a, b) asm("fma.rn.f32x2 %0, %1, %2, %0;" : "+l"(d) : "l"(a), "l"(b))

#if HAS_TCGEN05
// ---------------- tcgen05 helpers (only in feature-complete pass) ----------
__device__ __forceinline__ uint32_t smem_u32(const void* p) {
    uint32_t a;
    asm("{ .reg .u64 t; cvta.to.shared.u64 t, %1; cvt.u32.u64 %0, t; }" : "=r"(a) : "l"(p));
    return a;
}
__device__ __forceinline__ void mbar_init(uint32_t mbar, uint32_t cnt) {
    asm volatile("mbarrier.init.shared.b64 [%0], %1;" :: "r"(mbar), "r"(cnt) : "memory");
}
__device__ __forceinline__ void mbar_wait(uint32_t mbar, uint32_t parity) {
    asm volatile(
        "{\n\t.reg .pred P;\n\t"
        "WL_%=:\n\t"
        "mbarrier.try_wait.parity.acquire.cta.shared::cta.b64 P, [%0], %1, 0x989680;\n\t"
        "@!P bra WL_%=;\n\t}"
        :: "r"(mbar), "r"(parity) : "memory");
}
#define TMEM_ALLOC(sptr, ncols) \
    asm volatile("tcgen05.alloc.cta_group::1.sync.aligned.shared::cta.b32 [%0], %1;" \
                 :: "r"(sptr), "r"(ncols) : "memory")
#define TMEM_RELINQ() \
    asm volatile("tcgen05.relinquish_alloc_permit.cta_group::1.sync.aligned;")
#define TMEM_DEALLOC(taddr, ncols) \
    asm volatile("tcgen05.dealloc.cta_group::1.sync.aligned.b32 %0, %1;" :: "r"(taddr), "r"(ncols))
#define TC_COMMIT(mbar) \
    asm volatile("tcgen05.commit.cta_group::1.mbarrier::arrive::one.shared::cluster.b64 [%0];" \
                 :: "r"(mbar) : "memory")
#define TC_FENCE_AFTER()  asm volatile("tcgen05.fence::after_thread_sync;" ::: "memory")
#define TC_FENCE_BEFORE() asm volatile("tcgen05.fence::before_thread_sync;" ::: "memory")
#define FENCE_ASYNC_SHARED() asm volatile("fence.proxy.async.shared::cta;" ::: "memory")
#define TC_WAIT_LD() asm volatile("tcgen05.wait::ld.sync.aligned;" ::: "memory")

#define TCGEN05_MMA_TF32(d_tmem, a_desc, b_desc, idesc, en) do {                         \
    unsigned _e = (en);                                                                  \
    asm volatile("{\n\t.reg .pred p;\n\tsetp.ne.u32 p, %4, 0;\n\t"                       \
        "tcgen05.mma.cta_group::1.kind::tf32 [%0], %1, %2, %3, {%5, %5, %5, %5}, p;\n\t}"\
        :: "r"(d_tmem), "l"(a_desc), "l"(b_desc), "r"(idesc), "r"(_e), "r"(0u)           \
        : "memory");                                                                     \
} while (0)

#define TC_LD_X32(r, taddr)                                                              \
    asm volatile("tcgen05.ld.sync.aligned.32x32b.x32.b32 "                               \
        "{%0,%1,%2,%3,%4,%5,%6,%7,%8,%9,%10,%11,%12,%13,%14,%15,"                        \
        "%16,%17,%18,%19,%20,%21,%22,%23,%24,%25,%26,%27,%28,%29,%30,%31}, [%32];"       \
        : "=r"((r)[0]), "=r"((r)[1]), "=r"((r)[2]), "=r"((r)[3]),                        \
          "=r"((r)[4]), "=r"((r)[5]), "=r"((r)[6]), "=r"((r)[7]),                        \
          "=r"((r)[8]), "=r"((r)[9]), "=r"((r)[10]), "=r"((r)[11]),                      \
          "=r"((r)[12]), "=r"((r)[13]), "=r"((r)[14]), "=r"((r)[15]),                    \
          "=r"((r)[16]), "=r"((r)[17]), "=r"((r)[18]), "=r"((r)[19]),                    \
          "=r"((r)[20]), "=r"((r)[21]), "=r"((r)[22]), "=r"((r)[23]),                    \
          "=r"((r)[24]), "=r"((r)[25]), "=r"((r)[26]), "=r"((r)[27]),                    \
          "=r"((r)[28]), "=r"((r)[29]), "=r"((r)[30]), "=r"((r)[31])                     \
        : "r"(taddr))

static __device__ __forceinline__ uint64_t make_desc(uint32_t addr) {
    const uint64_t base = (uint64_t(2) << 61) | (uint64_t(1) << 46)
                        | (uint64_t(64) << 32) | (uint64_t(1) << 16);
    return base | ((uint64_t)(addr >> 4) & 0x3FFF);
}
// idesc kind::tf32: dtype=F32(1)<<4, atype=TF32(2)<<7, btype=TF32(2)<<10,
// N/8=8 <<17, M/16=8 <<24  -> M=128, N=64
#define IDESC_TF32 0x8100910u
#endif  // HAS_TCGEN05

// tcgen05 smem layout (bytes)
#define A_HI   0
#define A_LO   32768
#define B_HI   65536
#define B_LO   81920
#define S_W4   98304
#define S_IX   100352
#define S_TPTR 102400
#define S_MBAR 102408
// fallback needs (2*64*130 + 2*64*64 + 128*4)*4 + 2048 = 103424
#define SMEM_BYTES 103456

// ---------------------------------------------------------------------------
// Main kernel: one (b,y) row per block, 384 threads. Dual-path body.
// ---------------------------------------------------------------------------
__global__ __launch_bounds__(384, 2) void deform_main(
    const float* __restrict__ offset,
    const float* __restrict__ bias,
    float* __restrict__ out)
{
    extern __shared__ char smc[];
    const int tid = threadIdx.x;
    const int bid = blockIdx.x;
    const int b = bid >> 7, y = bid & 127;
    const float* xb   = g_xt + (size_t)b * HW * Cc;
    const float* offb = offset + (size_t)b * (2 * KK) * HW + (size_t)y * Ww;

#if HAS_TCGEN05
    // ====================== tcgen05 tf32 split path ======================
    const uint32_t sbase = smem_u32(smc);
    float* s_w4 = (float*)(smc + S_W4);
    int*   s_ix = (int*)(smc + S_IX);
    const int wid = tid >> 5, lid = tid & 31;

    if (wid == 0) { TMEM_ALLOC(sbase + S_TPTR, 64); TMEM_RELINQ(); }
    if (tid == 0) mbar_init(sbase + S_MBAR, 1);
    __syncthreads();
    uint32_t tmem;
    asm volatile("ld.shared.b32 %0, [%1];" : "=r"(tmem) : "r"(sbase + S_TPTR));

    int ph = 0;
    for (int t = 0; t < KK; ++t) {
        if (t) { mbar_wait(sbase + S_MBAR, ph); ph ^= 1; }   // tap t-1 MMAs done

        if (tid < 128) {
            int xx = tid;
            float ox = offb[(size_t)(2 * t)     * HW + xx];
            float oy = offb[(size_t)(2 * t + 1) * HW + xx];
            float pxf = (float)xx + ox, pyf = (float)y + oy;
            float x0f = floorf(pxf), y0f = floorf(pyf);
            float fx = pxf - x0f, fy = pyf - y0f;
            int x0 = (int)x0f, y0 = (int)y0f;
            int x1 = x0 + 1,   y1 = y0 + 1;
            float vx0 = (x0 >= 0 && x0 < Ww) ? 1.f : 0.f;
            float vx1 = (x1 >= 0 && x1 < Ww) ? 1.f : 0.f;
            float vy0 = (y0 >= 0 && y0 < Hh) ? 1.f : 0.f;
            float vy1 = (y1 >= 0 && y1 < Hh) ? 1.f : 0.f;
            int cx0 = min(max(x0, 0), Ww - 1), cx1 = min(max(x1, 0), Ww - 1);
            int cy0 = min(max(y0, 0), Hh - 1), cy1 = min(max(y1, 0), Hh - 1);
            s_w4[xx * 4 + 0] = (1.f - fx) * (1.f - fy) * vx0 * vy0;
            s_w4[xx * 4 + 1] = fx * (1.f - fy) * vx1 * vy0;
            s_w4[xx * 4 + 2] = (1.f - fx) * fy * vx0 * vy1;
            s_w4[xx * 4 + 3] = fx * fy * vx1 * vy1;
            s_ix[xx * 4 + 0] = cy0 * Ww + cx0;
            s_ix[xx * 4 + 1] = cy0 * Ww + cx1;
            s_ix[xx * 4 + 2] = cy1 * Ww + cx0;
            s_ix[xx * 4 + 3] = cy1 * Ww + cx1;
        }
        {   // stage pre-swizzled B tiles: 2 x 1024 float4
            const float4* sh = (const float4*)(g_wt_hi + t * 4096);
            const float4* sl = (const float4*)(g_wt_lo + t * 4096);
            float4* dh = (float4*)(smc + B_HI);
            float4* dl = (float4*)(smc + B_LO);
            for (int i = tid; i < 1024; i += 384) { dh[i] = sh[i]; dl[i] = sl[i]; }
        }
        __syncthreads();

        // gather + bilinear + tf32 split -> A tiles (blocked SW128 layout)
        for (int task = tid; task < 2048; task += 384) {
            int gpx = task >> 4, cg = task & 15;
            float w0 = s_w4[gpx * 4 + 0], w1 = s_w4[gpx * 4 + 1];
            float w2 = s_w4[gpx * 4 + 2], w3 = s_w4[gpx * 4 + 3];
            int i0 = s_ix[gpx * 4 + 0], i1 = s_ix[gpx * 4 + 1];
            int i2 = s_ix[gpx * 4 + 2], i3 = s_ix[gpx * 4 + 3];
            float4 v0 = *((const float4*)(xb + ((size_t)i0 << 6)) + cg);
            float4 v1 = *((const float4*)(xb + ((size_t)i1 << 6)) + cg);
            float4 v2 = *((const float4*)(xb + ((size_t)i2 << 6)) + cg);
            float4 v3 = *((const float4*)(xb + ((size_t)i3 << 6)) + cg);
            float s0 = fmaf(w3, v3.x, fmaf(w2, v2.x, fmaf(w1, v1.x, w0 * v0.x)));
            float s1 = fmaf(w3, v3.y, fmaf(w2, v2.y, fmaf(w1, v1.y, w0 * v0.y)));
            float s2 = fmaf(w3, v3.z, fmaf(w2, v2.z, fmaf(w1, v1.z, w0 * v0.z)));
            float s3 = fmaf(w3, v3.w, fmaf(w2, v2.w, fmaf(w1, v1.w, w0 * v0.w)));
            float h0 = tf32_rna(s0), h1 = tf32_rna(s1);
            float h2 = tf32_rna(s2), h3 = tf32_rna(s3);
            int c0 = cg * 4;
            uint32_t off = (uint32_t)(((gpx >> 3) + (c0 >> 5) * 16) * 1024
                                      + (gpx & 7) * 128 + (c0 & 31) * 4);
            uint32_t sw = sw128(off);
            *(float4*)(smc + A_HI + sw) = make_float4(h0, h1, h2, h3);
            *(float4*)(smc + A_LO + sw) = make_float4(s0 - h0, s1 - h1, s2 - h2, s3 - h3);
        }
        TC_FENCE_BEFORE();
        __syncthreads();

        if (tid == 0) {
            FENCE_ASYNC_SHARED();
            TC_FENCE_AFTER();
            uint64_t aHi = make_desc(sbase + A_HI), aLo = make_desc(sbase + A_LO);
            uint64_t bHi = make_desc(sbase + B_HI), bLo = make_desc(sbase + B_LO);
#pragma unroll
            for (int q = 0; q < 8; ++q) {               // K chunks of 8 tf32
                uint64_t ao = (uint64_t)((q >> 2) * 1024 + (q & 3) * 2);
                uint64_t bo = (uint64_t)((q >> 2) * 512  + (q & 3) * 2);
                TCGEN05_MMA_TF32(tmem, aHi + ao, bHi + bo, IDESC_TF32,
                                 (t > 0 || q > 0) ? 1u : 0u);
                TCGEN05_MMA_TF32(tmem, aHi + ao, bLo + bo, IDESC_TF32, 1u);
                TCGEN05_MMA_TF32(tmem, aLo + ao, bHi + bo, IDESC_TF32, 1u);
            }
            TC_COMMIT(sbase + S_MBAR);
        }
    }

    mbar_wait(sbase + S_MBAR, ph);
    TC_FENCE_AFTER();

    if (wid < 4) {
        uint32_t r[64];
        TC_LD_X32(r, tmem);
        TC_LD_X32(r + 32, tmem + 32);
        TC_WAIT_LD();
        TC_FENCE_BEFORE();
        int px = wid * 32 + lid;
        float* outb = out + ((size_t)b * Oo * Hh + y) * Ww + px;
#pragma unroll
        for (int o = 0; o < Oo; ++o)
            outb[(size_t)o * HW] = __uint_as_float(r[o]) + __ldg(bias + o);
    }
    __syncthreads();
    if (wid == 0) TMEM_DEALLOC(tmem, 64);

#else
    // ====================== FFMA2 fallback path (round-2) ======================
    float* smem = (float*)smc;
    float* sms  = smem;                        // 2 x [64][SPAD]
    float* smw  = smem + 2 * 64 * SPAD;        // 2 x [64][64]
    float* smw4 = smw + 2 * 64 * 64;           // [128][4]
    int*   smix = (int*)(smw4 + 128 * 4);      // [128][4]

    const bool producer = (tid >= 256);
    const int ptid = tid - 256;
    const int px0 = (tid & 31) * 4;
    const int o0  = (tid >> 5) * 8;

    unsigned long long acc[16];
#pragma unroll
    for (int i = 0; i < 16; ++i) acc[i] = 0ull;

    auto produce = [&](int tt) {
        float* sdst = sms + (tt & 1) * 64 * SPAD;
        {
            int xx = ptid;
            float ox = offb[(size_t)(2 * tt)     * HW + xx];
            float oy = offb[(size_t)(2 * tt + 1) * HW + xx];
            float pxf = (float)xx + ox;
            float pyf = (float)y  + oy;
            float x0f = floorf(pxf), y0f = floorf(pyf);
            float fx = pxf - x0f, fy = pyf - y0f;
            int x0 = (int)x0f, y0 = (int)y0f;
            int x1 = x0 + 1,   y1 = y0 + 1;
            float vx0 = (x0 >= 0 && x0 < Ww) ? 1.f : 0.f;
            float vx1 = (x1 >= 0 && x1 < Ww) ? 1.f : 0.f;
            float vy0 = (y0 >= 0 && y0 < Hh) ? 1.f : 0.f;
            float vy1 = (y1 >= 0 && y1 < Hh) ? 1.f : 0.f;
            int cx0 = min(max(x0, 0), Ww - 1), cx1 = min(max(x1, 0), Ww - 1);
            int cy0 = min(max(y0, 0), Hh - 1), cy1 = min(max(y1, 0), Hh - 1);
            smw4[xx * 4 + 0] = (1.f - fx) * (1.f - fy) * vx0 * vy0;
            smw4[xx * 4 + 1] = fx * (1.f - fy) * vx1 * vy0;
            smw4[xx * 4 + 2] = (1.f - fx) * fy * vx0 * vy1;
            smw4[xx * 4 + 3] = fx * fy * vx1 * vy1;
            smix[xx * 4 + 0] = cy0 * Ww + cx0;
            smix[xx * 4 + 1] = cy0 * Ww + cx1;
            smix[xx * 4 + 2] = cy1 * Ww + cx0;
            smix[xx * 4 + 3] = cy1 * Ww + cx1;
        }
        {
            const float4* wsrc = (const float4*)(g_wt + (size_t)tt * Cc * Oo);
            float4* wdst = (float4*)(smw + (tt & 1) * 64 * 64);
#pragma unroll
            for (int i = 0; i < 8; ++i) wdst[ptid + i * 128] = wsrc[ptid + i * 128];
        }
        asm volatile("bar.sync 1, 128;" ::: "memory");
#pragma unroll 4
        for (int it = 0; it < 16; ++it) {
            int task = it * 128 + ptid;
            int gpx = task >> 4, cg = task & 15;
            float w0 = smw4[gpx * 4 + 0], w1 = smw4[gpx * 4 + 1];
            float w2 = smw4[gpx * 4 + 2], w3 = smw4[gpx * 4 + 3];
            int i0 = smix[gpx * 4 + 0], i1 = smix[gpx * 4 + 1];
            int i2 = smix[gpx * 4 + 2], i3 = smix[gpx * 4 + 3];
            float4 v0 = *((const float4*)(xb + ((size_t)i0 << 6)) + cg);
            float4 v1 = *((const float4*)(xb + ((size_t)i1 << 6)) + cg);
            float4 v2 = *((const float4*)(xb + ((size_t)i2 << 6)) + cg);
            float4 v3 = *((const float4*)(xb + ((size_t)i3 << 6)) + cg);
            float s0 = fmaf(w3, v3.x, fmaf(w2, v2.x, fmaf(w1, v1.x, w0 * v0.x)));
            float s1 = fmaf(w3, v3.y, fmaf(w2, v2.y, fmaf(w1, v1.y, w0 * v0.y)));
            float s2 = fmaf(w3, v3.z, fmaf(w2, v2.z, fmaf(w1, v1.z, w0 * v0.z)));
            float s3 = fmaf(w3, v3.w, fmaf(w2, v2.w, fmaf(w1, v1.w, w0 * v0.w)));
            float* dc = sdst + (cg * 4) * SPAD + gpx;
            dc[0 * SPAD] = s0;
            dc[1 * SPAD] = s1;
            dc[2 * SPAD] = s2;
            dc[3 * SPAD] = s3;
        }
    };

    if (producer) produce(0);
    __syncthreads();

    for (int t = 0; t < KK; ++t) {
        if (producer) {
            if (t + 1 < KK) produce(t + 1);
        } else {
            const float* sb = sms + (t & 1) * 64 * SPAD + px0;
            const float* sw = smw + (t & 1) * 64 * 64 + o0;
#pragma unroll 2
            for (int c = 0; c < 64; ++c) {
                unsigned long long p01 = *(const unsigned long long*)(sb + c * SPAD);
                unsigned long long p23 = *(const unsigned long long*)(sb + c * SPAD + 2);
                ulonglong2 wA = *(const ulonglong2*)(sw + c * 64);
                ulonglong2 wB = *(const ulonglong2*)(sw + c * 64 + 4);
                unsigned s0, s1, s2, s3;
                asm("mov.b64 {%0,%1}, %2;" : "=r"(s0), "=r"(s1) : "l"(p01));
                asm("mov.b64 {%0,%1}, %2;" : "=r"(s2), "=r"(s3) : "l"(p23));
                unsigned long long d0, d1, d2, d3;
                asm("mov.b64 %0, {%1,%1};" : "=l"(d0) : "r"(s0));
                asm("mov.b64 %0, {%1,%1};" : "=l"(d1) : "r"(s1));
                asm("mov.b64 %0, {%1,%1};" : "=l"(d2) : "r"(s2));
                asm("mov.b64 %0, {%1,%1};" : "=l"(d3) : "r"(s3));
                FMA2(acc[0],  wA.x, d0); FMA2(acc[1],  wA.y, d0);
                FMA2(acc[2],  wB.x, d0); FMA2(acc[3],  wB.y, d0);
                FMA2(acc[4],  wA.x, d1); FMA2(acc[5],  wA.y, d1);
                FMA2(acc[6],  wB.x, d1); FMA2(acc[7],  wB.y, d1);
                FMA2(acc[8],  wA.x, d2); FMA2(acc[9],  wA.y, d2);
                FMA2(acc[10], wB.x, d2); FMA2(acc[11], wB.y, d2);
                FMA2(acc[12], wA.x, d3); FMA2(acc[13], wA.y, d3);
                FMA2(acc[14], wB.x, d3); FMA2(acc[15], wB.y, d3);
            }
        }
        __syncthreads();
    }

    if (!producer) {
        float* stg = sms;
#pragma unroll
        for (int k = 0; k < 4; ++k) {
            float blo = bias[o0 + 2 * k];
            float bhi = bias[o0 + 2 * k + 1];
#pragma unroll
            for (int i = 0; i < 4; ++i) {
                unsigned long long a = acc[i * 4 + k];
                float lo = __uint_as_float((unsigned)(a & 0xffffffffull));
                float hi = __uint_as_float((unsigned)(a >> 32));
                stg[(o0 + 2 * k) * OSTRIDE + px0 + i]     = lo + blo;
                stg[(o0 + 2 * k + 1) * OSTRIDE + px0 + i] = hi + bhi;
            }
        }
    }
    __syncthreads();
    {
        float* outb = out + ((size_t)b * Oo * Hh + y) * Ww;
        const float* stg = sms;
        for (int idx = tid; idx < Oo * Ww / 4; idx += 384) {
            int o = idx >> 5, q = idx & 31;
            float4 v = *(const float4*)(stg + o * OSTRIDE + q * 4);
            *(float4*)(outb + (size_t)o * HW + q * 4) = v;
        }
    }
#endif
}

extern "C" void kernel_launch(void* const* d_in, const int* in_sizes, int n_in,
                              void* d_out, int out_size) {
    const float* x      = (const float*)d_in[0];
    const float* offset = (const float*)d_in[1];
    const float* weight = (const float*)d_in[2];
    const float* bias   = (const float*)d_in[3];
    float* out = (float*)d_out;

    transpose_x_kernel<<<Bb * Hh * 2, 128>>>(x);
    prep_w_kernel<<<(KK * 4096 + 255) / 256, 256>>>(weight);

    cudaFuncSetAttribute(deform_main, cudaFuncAttributeMaxDynamicSharedMemorySize,
                         SMEM_BYTES);
    deform_main<<<Bb * Hh, 384, SMEM_BYTES>>>(offset, bias, out);
}

// round 5
// speedup vs baseline: 2.9137x; 1.2976x over previous
#include <cuda_runtime.h>
#include <cuda_bf16.h>
#include <cstdint>

#define Hh 128
#define Ww 128
#define Cc 64
#define Oo 64
#define KK 9
#define Bb 4
#define HW (Hh * Ww)

#define SPAD 130                 // fallback s tile row stride
#define OSTRIDE 132              // fallback epilogue staging stride

// ---------------- scratch (no allocs allowed) ----------------
__device__ float g_xt[(size_t)Bb * HW * Cc];        // NHWC image [b][y][x][c]
__device__ float g_wt[KK * Cc * Oo];                // fallback: [t][c][o]
__device__ uint4 g_wb_hi[KK * 512];                 // per-tap B tile [o=64][c=64] bf16-hi, SW128 pre-swizzled (8KB/tap)
__device__ uint4 g_wb_lo[KK * 512];                 // bf16-lo residual

// Is the current device-compile pass feature-complete sm_103a?
#if defined(__CUDA_ARCH__) && (defined(__CUDA_ARCH_FEAT_SM103_ALL) || defined(__CUDA_ARCH_FEAT_SM100_ALL))
#define HAS_TCGEN05 1
#else
#define HAS_TCGEN05 0
#endif

__device__ __forceinline__ uint32_t sw128(uint32_t off) { return off ^ ((off >> 3) & 0x70); }

// ---------------------------------------------------------------------------
// x: [b][c][y][x] -> g_xt: [b][y][x][c]. 1024 blocks x 128 thr, tile 32c x 128x
// ---------------------------------------------------------------------------
__global__ __launch_bounds__(128) void transpose_x_kernel(const float* __restrict__ x) {
    __shared__ float tile[32][129];
    int blk = blockIdx.x;                // b*256 + y*2 + half
    int b = blk >> 8;
    int rem = blk & 255;
    int y = rem >> 1;
    int c0 = (rem & 1) * 32;
    const float* src = x + ((size_t)(b * Cc + c0)) * HW + (size_t)y * Ww;
    int t = threadIdx.x;
#pragma unroll
    for (int k = 0; k < 8; ++k) {
        int i = t + k * 128;             // 32 c * 32 x4-groups
        int c = i >> 5, x4 = i & 31;
        float4 v = *(const float4*)(src + (size_t)c * HW + x4 * 4);
        tile[c][x4 * 4 + 0] = v.x; tile[c][x4 * 4 + 1] = v.y;
        tile[c][x4 * 4 + 2] = v.z; tile[c][x4 * 4 + 3] = v.w;
    }
    __syncthreads();
    float* dst = g_xt + ((size_t)(b * Hh + y) * Ww) * Cc + c0;
#pragma unroll
    for (int k = 0; k < 8; ++k) {
        int i = t + k * 128;             // 128 x * 8 c4-groups
        int xx = i >> 3, c4 = i & 7;
        float4 v = make_float4(tile[c4 * 4 + 0][xx], tile[c4 * 4 + 1][xx],
                               tile[c4 * 4 + 2][xx], tile[c4 * 4 + 3][xx]);
        *(float4*)(dst + (size_t)xx * Cc + c4 * 4) = v;
    }
}

// ---------------------------------------------------------------------------
// weight prep: fallback [t][c][o] AND bf16 hi/lo SW128 B tiles ([o][c], 128B/row)
// ---------------------------------------------------------------------------
__global__ void prep_w_kernel(const float* __restrict__ w) {
    int i = blockIdx.x * blockDim.x + threadIdx.x;
    if (i >= KK * 4096) return;
    int t = i >> 12, r = i & 4095;
    int o = r >> 6, c = r & 63;
    float val = w[(o * Cc + c) * KK + t];
    g_wt[t * 4096 + c * 64 + o] = val;                 // fallback layout
    __nv_bfloat16 h = __float2bfloat16(val);
    float hf = __bfloat162float(h);
    __nv_bfloat16 l = __float2bfloat16(val - hf);
    uint32_t off = (uint32_t)(o * 128 + c * 2);        // bytes within tile
    uint32_t sw = sw128(off) >> 1;                     // uint16 index
    ((unsigned short*)g_wb_hi)[t * 4096 + sw] = __bfloat16_as_ushort(h);
    ((unsigned short*)g_wb_lo)[t * 4096 + sw] = __bfloat16_as_ushort(l);
}

// packed f32x2 FMA: d = a*b + d
#define FMA2(d, a, b) asm("fma.rn.f32x2 %0, %1, %2, %0;" : "+l"(d) : "l"(a), "l"(b))

#if HAS_TCGEN05
// ---------------- tcgen05 helpers (only in feature-complete pass) ----------
__device__ __forceinline__ uint32_t smem_u32(const void* p) {
    uint32_t a;
    asm("{ .reg .u64 t; cvta.to.shared.u64 t, %1; cvt.u32.u64 %0, t; }" : "=r"(a) : "l"(p));
    return a;
}
__device__ __forceinline__ void mbar_init(uint32_t mbar, uint32_t cnt) {
    asm volatile("mbarrier.init.shared.b64 [%0], %1;" :: "r"(mbar), "r"(cnt) : "memory");
}
__device__ __forceinline__ void mbar_wait(uint32_t mbar, uint32_t parity) {
    asm volatile(
        "{\n\t.reg .pred P;\n\t"
        "WL_%=:\n\t"
        "mbarrier.try_wait.parity.acquire.cta.shared::cta.b64 P, [%0], %1, 0x989680;\n\t"
        "@!P bra WL_%=;\n\t}"
        :: "r"(mbar), "r"(parity) : "memory");
}
#define TMEM_ALLOC(sptr, ncols) \
    asm volatile("tcgen05.alloc.cta_group::1.sync.aligned.shared::cta.b32 [%0], %1;" \
                 :: "r"(sptr), "r"(ncols) : "memory")
#define TMEM_RELINQ() \
    asm volatile("tcgen05.relinquish_alloc_permit.cta_group::1.sync.aligned;")
#define TMEM_DEALLOC(taddr, ncols) \
    asm volatile("tcgen05.dealloc.cta_group::1.sync.aligned.b32 %0, %1;" :: "r"(taddr), "r"(ncols))
#define TC_COMMIT(mbar) \
    asm volatile("tcgen05.commit.cta_group::1.mbarrier::arrive::one.shared::cluster.b64 [%0];" \
                 :: "r"(mbar) : "memory")
#define TC_FENCE_AFTER()  asm volatile("tcgen05.fence::after_thread_sync;" ::: "memory")
#define TC_FENCE_BEFORE() asm volatile("tcgen05.fence::before_thread_sync;" ::: "memory")
#define FENCE_ASYNC_SHARED() asm volatile("fence.proxy.async.shared::cta;" ::: "memory")
#define TC_WAIT_LD() asm volatile("tcgen05.wait::ld.sync.aligned;" ::: "memory")

#define TCGEN05_MMA_BF16(d_tmem, a_desc, b_desc, idesc, en) do {                         \
    unsigned _e = (en);                                                                  \
    asm volatile("{\n\t.reg .pred p;\n\tsetp.ne.u32 p, %4, 0;\n\t"                       \
        "tcgen05.mma.cta_group::1.kind::f16 [%0], %1, %2, %3, {%5, %5, %5, %5}, p;\n\t}" \
        :: "r"(d_tmem), "l"(a_desc), "l"(b_desc), "r"(idesc), "r"(_e), "r"(0u)           \
        : "memory");                                                                     \
} while (0)

#define TC_LD_X32(r, taddr)                                                              \
    asm volatile("tcgen05.ld.sync.aligned.32x32b.x32.b32 "                               \
        "{%0,%1,%2,%3,%4,%5,%6,%7,%8,%9,%10,%11,%12,%13,%14,%15,"                        \
        "%16,%17,%18,%19,%20,%21,%22,%23,%24,%25,%26,%27,%28,%29,%30,%31}, [%32];"       \
        : "=r"((r)[0]), "=r"((r)[1]), "=r"((r)[2]), "=r"((r)[3]),                        \
          "=r"((r)[4]), "=r"((r)[5]), "=r"((r)[6]), "=r"((r)[7]),                        \
          "=r"((r)[8]), "=r"((r)[9]), "=r"((r)[10]), "=r"((r)[11]),                      \
          "=r"((r)[12]), "=r"((r)[13]), "=r"((r)[14]), "=r"((r)[15]),                    \
          "=r"((r)[16]), "=r"((r)[17]), "=r"((r)[18]), "=r"((r)[19]),                    \
          "=r"((r)[20]), "=r"((r)[21]), "=r"((r)[22]), "=r"((r)[23]),                    \
          "=r"((r)[24]), "=r"((r)[25]), "=r"((r)[26]), "=r"((r)[27]),                    \
          "=r"((r)[28]), "=r"((r)[29]), "=r"((r)[30]), "=r"((r)[31])                     \
        : "r"(taddr))

static __device__ __forceinline__ uint64_t make_desc(uint32_t addr) {
    const uint64_t base = (uint64_t(2) << 61) | (uint64_t(1) << 46)
                        | (uint64_t(64) << 32) | (uint64_t(1) << 16);
    return base | ((uint64_t)(addr >> 4) & 0x3FFF);
}
// idesc kind::f16: dtype=F32(1)<<4, atype=BF16(1)<<7, btype=BF16(1)<<10,
// N/8=8 <<17, M/16=8 <<24  -> M=128, N=64
#define IDESC_BF16 0x8100490u
#endif  // HAS_TCGEN05

// tcgen05 smem layout (bytes): two buffers, each A_hi|A_lo|B_hi|B_lo
#define BUF_STRIDE 49152
#define A_HI   0
#define A_LO   16384
#define B_HI   32768
#define B_LO   40960
#define S_W4   98304
#define S_IX   100352
#define S_TPTR 102400
#define S_MBAR0 102408
#define S_MBAR1 102416
// fallback needs (2*64*130 + 2*64*64 + 128*4)*4 + 2048 = 103424
#define SMEM_BYTES 103456

// ---------------------------------------------------------------------------
// Main kernel: one (b,y) row per block, 384 threads. Dual-path body.
// ---------------------------------------------------------------------------
__global__ __launch_bounds__(384, 2) void deform_main(
    const float* __restrict__ offset,
    const float* __restrict__ bias,
    float* __restrict__ out)
{
    extern __shared__ char smc[];
    const int tid = threadIdx.x;
    const int bid = blockIdx.x;
    const int b = bid >> 7, y = bid & 127;
    const float* xb   = g_xt + (size_t)b * HW * Cc;
    const float* offb = offset + (size_t)b * (2 * KK) * HW + (size_t)y * Ww;

#if HAS_TCGEN05
    // ============ tcgen05 bf16 3-term split, double-buffered pipeline ============
    const uint32_t sbase = smem_u32(smc);
    float* s_w4 = (float*)(smc + S_W4);
    int*   s_ix = (int*)(smc + S_IX);
    const int wid = tid >> 5, lid = tid & 31;

    if (wid == 0) { TMEM_ALLOC(sbase + S_TPTR, 64); TMEM_RELINQ(); }
    if (tid == 0) { mbar_init(sbase + S_MBAR0, 1); mbar_init(sbase + S_MBAR1, 1); }
    __syncthreads();
    uint32_t tmem;
    asm volatile("ld.shared.b32 %0, [%1];" : "=r"(tmem) : "r"(sbase + S_TPTR));

    int ph0 = 0, ph1 = 0;
    for (int t = 0; t < KK; ++t) {
        const int buf = t & 1;
        const uint32_t bufo = buf * BUF_STRIDE;
        const uint32_t mb = sbase + (buf ? S_MBAR1 : S_MBAR0);
        if (t >= 2) {   // buffer reused: wait for tap t-2's MMAs to complete
            if (buf == 0) { mbar_wait(mb, ph0); ph0 ^= 1; }
            else          { mbar_wait(mb, ph1); ph1 ^= 1; }
        }

        // ---- coords for 128 pixels (threads 0..127) ----
        if (tid < 128) {
            int xx = tid;
            float ox = offb[(size_t)(2 * t)     * HW + xx];
            float oy = offb[(size_t)(2 * t + 1) * HW + xx];
            float pxf = (float)xx + ox, pyf = (float)y + oy;
            float x0f = floorf(pxf), y0f = floorf(pyf);
            float fx = pxf - x0f, fy = pyf - y0f;
            int x0 = (int)x0f, y0 = (int)y0f;
            int x1 = x0 + 1,   y1 = y0 + 1;
            float vx0 = (x0 >= 0 && x0 < Ww) ? 1.f : 0.f;
            float vx1 = (x1 >= 0 && x1 < Ww) ? 1.f : 0.f;
            float vy0 = (y0 >= 0 && y0 < Hh) ? 1.f : 0.f;
            float vy1 = (y1 >= 0 && y1 < Hh) ? 1.f : 0.f;
            int cx0 = min(max(x0, 0), Ww - 1), cx1 = min(max(x1, 0), Ww - 1);
            int cy0 = min(max(y0, 0), Hh - 1), cy1 = min(max(y1, 0), Hh - 1);
            s_w4[xx * 4 + 0] = (1.f - fx) * (1.f - fy) * vx0 * vy0;
            s_w4[xx * 4 + 1] = fx * (1.f - fy) * vx1 * vy0;
            s_w4[xx * 4 + 2] = (1.f - fx) * fy * vx0 * vy1;
            s_w4[xx * 4 + 3] = fx * fy * vx1 * vy1;
            s_ix[xx * 4 + 0] = cy0 * Ww + cx0;
            s_ix[xx * 4 + 1] = cy0 * Ww + cx1;
            s_ix[xx * 4 + 2] = cy1 * Ww + cx0;
            s_ix[xx * 4 + 3] = cy1 * Ww + cx1;
        }
        {   // stage pre-swizzled bf16 B tiles: 2 x 512 uint4
            const uint4* sh = g_wb_hi + t * 512;
            const uint4* sl = g_wb_lo + t * 512;
            uint4* dh = (uint4*)(smc + bufo + B_HI);
            uint4* dl = (uint4*)(smc + bufo + B_LO);
            for (int i = tid; i < 512; i += 384) { dh[i] = sh[i]; dl[i] = sl[i]; }
        }
        __syncthreads();

        // ---- gather + bilinear + bf16 split -> A tiles (SW128, 128B/row) ----
        char* aHiP = smc + bufo + A_HI;
        char* aLoP = smc + bufo + A_LO;
#pragma unroll
        for (int it = 0; it < 6; ++it) {
            int task = it * 384 + tid;           // 2048 = 384*5 + 128
            if (it == 5 && tid >= 128) break;
            int gpx = task >> 4, cg = task & 15;
            float w0 = s_w4[gpx * 4 + 0], w1 = s_w4[gpx * 4 + 1];
            float w2 = s_w4[gpx * 4 + 2], w3 = s_w4[gpx * 4 + 3];
            int i0 = s_ix[gpx * 4 + 0], i1 = s_ix[gpx * 4 + 1];
            int i2 = s_ix[gpx * 4 + 2], i3 = s_ix[gpx * 4 + 3];
            float4 v0 = *((const float4*)(xb + ((size_t)i0 << 6)) + cg);
            float4 v1 = *((const float4*)(xb + ((size_t)i1 << 6)) + cg);
            float4 v2 = *((const float4*)(xb + ((size_t)i2 << 6)) + cg);
            float4 v3 = *((const float4*)(xb + ((size_t)i3 << 6)) + cg);
            float s0 = fmaf(w3, v3.x, fmaf(w2, v2.x, fmaf(w1, v1.x, w0 * v0.x)));
            float s1 = fmaf(w3, v3.y, fmaf(w2, v2.y, fmaf(w1, v1.y, w0 * v0.y)));
            float s2 = fmaf(w3, v3.z, fmaf(w2, v2.z, fmaf(w1, v1.z, w0 * v0.z)));
            float s3 = fmaf(w3, v3.w, fmaf(w2, v2.w, fmaf(w1, v1.w, w0 * v0.w)));
            uint32_t h01, h23, l01, l23;
            asm("cvt.rn.bf16x2.f32 %0, %1, %2;" : "=r"(h01) : "f"(s1), "f"(s0));
            asm("cvt.rn.bf16x2.f32 %0, %1, %2;" : "=r"(h23) : "f"(s3), "f"(s2));
            float f0 = __uint_as_float(h01 << 16);
            float f1 = __uint_as_float(h01 & 0xffff0000u);
            float f2 = __uint_as_float(h23 << 16);
            float f3 = __uint_as_float(h23 & 0xffff0000u);
            float r0 = s0 - f0, r1 = s1 - f1, r2 = s2 - f2, r3 = s3 - f3;
            asm("cvt.rn.bf16x2.f32 %0, %1, %2;" : "=r"(l01) : "f"(r1), "f"(r0));
            asm("cvt.rn.bf16x2.f32 %0, %1, %2;" : "=r"(l23) : "f"(r3), "f"(r2));
            uint32_t sw = sw128((uint32_t)(gpx * 128 + cg * 8));
            *(uint2*)(aHiP + sw) = make_uint2(h01, h23);
            *(uint2*)(aLoP + sw) = make_uint2(l01, l23);
        }
        TC_FENCE_BEFORE();
        __syncthreads();

        // ---- MMAs: 4 K-chunks x 3 split terms, single commit ----
        if (tid == 0) {
            FENCE_ASYNC_SHARED();
            TC_FENCE_AFTER();
            uint64_t aHi = make_desc(sbase + bufo + A_HI);
            uint64_t aLo = make_desc(sbase + bufo + A_LO);
            uint64_t bHi = make_desc(sbase + bufo + B_HI);
            uint64_t bLo = make_desc(sbase + bufo + B_LO);
#pragma unroll
            for (int q = 0; q < 4; ++q) {        // K chunks of 16 bf16 = +2 units
                uint64_t o2 = (uint64_t)(q * 2);
                TCGEN05_MMA_BF16(tmem, aHi + o2, bHi + o2, IDESC_BF16,
                                 (t > 0 || q > 0) ? 1u : 0u);
                TCGEN05_MMA_BF16(tmem, aHi + o2, bLo + o2, IDESC_BF16, 1u);
                TCGEN05_MMA_BF16(tmem, aLo + o2, bHi + o2, IDESC_BF16, 1u);
            }
            TC_COMMIT(mb);
        }
    }

    // final commit was to mb0 (tap 8); it tracks ALL prior MMAs from tid 0
    mbar_wait(sbase + S_MBAR0, ph0);
    TC_FENCE_AFTER();

    if (wid < 4) {
        uint32_t r[64];
        TC_LD_X32(r, tmem);
        TC_LD_X32(r + 32, tmem + 32);
        TC_WAIT_LD();
        TC_FENCE_BEFORE();
        int px = wid * 32 + lid;
        float* outb = out + ((size_t)b * Oo * Hh + y) * Ww + px;
#pragma unroll
        for (int o = 0; o < Oo; ++o)
            outb[(size_t)o * HW] = __uint_as_float(r[o]) + __ldg(bias + o);
    }
    __syncthreads();
    if (wid == 0) TMEM_DEALLOC(tmem, 64);

#else
    // ====================== FFMA2 fallback path (round-2) ======================
    float* smem = (float*)smc;
    float* sms  = smem;                        // 2 x [64][SPAD]
    float* smw  = smem + 2 * 64 * SPAD;        // 2 x [64][64]
    float* smw4 = smw + 2 * 64 * 64;           // [128][4]
    int*   smix = (int*)(smw4 + 128 * 4);      // [128][4]

    const bool producer = (tid >= 256);
    const int ptid = tid - 256;
    const int px0 = (tid & 31) * 4;
    const int o0  = (tid >> 5) * 8;

    unsigned long long acc[16];
#pragma unroll
    for (int i = 0; i < 16; ++i) acc[i] = 0ull;

    auto produce = [&](int tt) {
        float* sdst = sms + (tt & 1) * 64 * SPAD;
        {
            int xx = ptid;
            float ox = offb[(size_t)(2 * tt)     * HW + xx];
            float oy = offb[(size_t)(2 * tt + 1) * HW + xx];
            float pxf = (float)xx + ox;
            float pyf = (float)y  + oy;
            float x0f = floorf(pxf), y0f = floorf(pyf);
            float fx = pxf - x0f, fy = pyf - y0f;
            int x0 = (int)x0f, y0 = (int)y0f;
            int x1 = x0 + 1,   y1 = y0 + 1;
            float vx0 = (x0 >= 0 && x0 < Ww) ? 1.f : 0.f;
            float vx1 = (x1 >= 0 && x1 < Ww) ? 1.f : 0.f;
            float vy0 = (y0 >= 0 && y0 < Hh) ? 1.f : 0.f;
            float vy1 = (y1 >= 0 && y1 < Hh) ? 1.f : 0.f;
            int cx0 = min(max(x0, 0), Ww - 1), cx1 = min(max(x1, 0), Ww - 1);
            int cy0 = min(max(y0, 0), Hh - 1), cy1 = min(max(y1, 0), Hh - 1);
            smw4[xx * 4 + 0] = (1.f - fx) * (1.f - fy) * vx0 * vy0;
            smw4[xx * 4 + 1] = fx * (1.f - fy) * vx1 * vy0;
            smw4[xx * 4 + 2] = (1.f - fx) * fy * vx0 * vy1;
            smw4[xx * 4 + 3] = fx * fy * vx1 * vy1;
            smix[xx * 4 + 0] = cy0 * Ww + cx0;
            smix[xx * 4 + 1] = cy0 * Ww + cx1;
            smix[xx * 4 + 2] = cy1 * Ww + cx0;
            smix[xx * 4 + 3] = cy1 * Ww + cx1;
        }
        {
            const float4* wsrc = (const float4*)(g_wt + (size_t)tt * Cc * Oo);
            float4* wdst = (float4*)(smw + (tt & 1) * 64 * 64);
#pragma unroll
            for (int i = 0; i < 8; ++i) wdst[ptid + i * 128] = wsrc[ptid + i * 128];
        }
        asm volatile("bar.sync 1, 128;" ::: "memory");
#pragma unroll 4
        for (int it = 0; it < 16; ++it) {
            int task = it * 128 + ptid;
            int gpx = task >> 4, cg = task & 15;
            float w0 = smw4[gpx * 4 + 0], w1 = smw4[gpx * 4 + 1];
            float w2 = smw4[gpx * 4 + 2], w3 = smw4[gpx * 4 + 3];
            int i0 = smix[gpx * 4 + 0], i1 = smix[gpx * 4 + 1];
            int i2 = smix[gpx * 4 + 2], i3 = smix[gpx * 4 + 3];
            float4 v0 = *((const float4*)(xb + ((size_t)i0 << 6)) + cg);
            float4 v1 = *((const float4*)(xb + ((size_t)i1 << 6)) + cg);
            float4 v2 = *((const float4*)(xb + ((size_t)i2 << 6)) + cg);
            float4 v3 = *((const float4*)(xb + ((size_t)i3 << 6)) + cg);
            float s0 = fmaf(w3, v3.x, fmaf(w2, v2.x, fmaf(w1, v1.x, w0 * v0.x)));
            float s1 = fmaf(w3, v3.y, fmaf(w2, v2.y, fmaf(w1, v1.y, w0 * v0.y)));
            float s2 = fmaf(w3, v3.z, fmaf(w2, v2.z, fmaf(w1, v1.z, w0 * v0.z)));
            float s3 = fmaf(w3, v3.w, fmaf(w2, v2.w, fmaf(w1, v1.w, w0 * v0.w)));
            float* dc = sdst + (cg * 4) * SPAD + gpx;
            dc[0 * SPAD] = s0;
            dc[1 * SPAD] = s1;
            dc[2 * SPAD] = s2;
            dc[3 * SPAD] = s3;
        }
    };

    if (producer) produce(0);
    __syncthreads();

    for (int t = 0; t < KK; ++t) {
        if (producer) {
            if (t + 1 < KK) produce(t + 1);
        } else {
            const float* sb = sms + (t & 1) * 64 * SPAD + px0;
            const float* sw = smw + (t & 1) * 64 * 64 + o0;
#pragma unroll 2
            for (int c = 0; c < 64; ++c) {
                unsigned long long p01 = *(const unsigned long long*)(sb + c * SPAD);
                unsigned long long p23 = *(const unsigned long long*)(sb + c * SPAD + 2);
                ulonglong2 wA = *(const ulonglong2*)(sw + c * 64);
                ulonglong2 wB = *(const ulonglong2*)(sw + c * 64 + 4);
                unsigned s0, s1, s2, s3;
                asm("mov.b64 {%0,%1}, %2;" : "=r"(s0), "=r"(s1) : "l"(p01));
                asm("mov.b64 {%0,%1}, %2;" : "=r"(s2), "=r"(s3) : "l"(p23));
                unsigned long long d0, d1, d2, d3;
                asm("mov.b64 %0, {%1,%1};" : "=l"(d0) : "r"(s0));
                asm("mov.b64 %0, {%1,%1};" : "=l"(d1) : "r"(s1));
                asm("mov.b64 %0, {%1,%1};" : "=l"(d2) : "r"(s2));
                asm("mov.b64 %0, {%1,%1};" : "=l"(d3) : "r"(s3));
                FMA2(acc[0],  wA.x, d0); FMA2(acc[1],  wA.y, d0);
                FMA2(acc[2],  wB.x, d0); FMA2(acc[3],  wB.y, d0);
                FMA2(acc[4],  wA.x, d1); FMA2(acc[5],  wA.y, d1);
                FMA2(acc[6],  wB.x, d1); FMA2(acc[7],  wB.y, d1);
                FMA2(acc[8],  wA.x, d2); FMA2(acc[9],  wA.y, d2);
                FMA2(acc[10], wB.x, d2); FMA2(acc[11], wB.y, d2);
                FMA2(acc[12], wA.x, d3); FMA2(acc[13], wA.y, d3);
                FMA2(acc[14], wB.x, d3); FMA2(acc[15], wB.y, d3);
            }
        }
        __syncthreads();
    }

    if (!producer) {
        float* stg = sms;
#pragma unroll
        for (int k = 0; k < 4; ++k) {
            float blo = bias[o0 + 2 * k];
            float bhi = bias[o0 + 2 * k + 1];
#pragma unroll
            for (int i = 0; i < 4; ++i) {
                unsigned long long a = acc[i * 4 + k];
                float lo = __uint_as_float((unsigned)(a & 0xffffffffull));
                float hi = __uint_as_float((unsigned)(a >> 32));
                stg[(o0 + 2 * k) * OSTRIDE + px0 + i]     = lo + blo;
                stg[(o0 + 2 * k + 1) * OSTRIDE + px0 + i] = hi + bhi;
            }
        }
    }
    __syncthreads();
    {
        float* outb = out + ((size_t)b * Oo * Hh + y) * Ww;
        const float* stg = sms;
        for (int idx = tid; idx < Oo * Ww / 4; idx += 384) {
            int o = idx >> 5, q = idx & 31;
            float4 v = *(const float4*)(stg + o * OSTRIDE + q * 4);
            *(float4*)(outb + (size_t)o * HW + q * 4) = v;
        }
    }
#endif
}

extern "C" void kernel_launch(void* const* d_in, const int* in_sizes, int n_in,
                              void* d_out, int out_size) {
    const float* x      = (const float*)d_in[0];
    const float* offset = (const float*)d_in[1];
    const float* weight = (const float*)d_in[2];
    const float* bias   = (const float*)d_in[3];
    float* out = (float*)d_out;

    transpose_x_kernel<<<Bb * Hh * 2, 128>>>(x);
    prep_w_kernel<<<(KK * 4096 + 255) / 256, 256>>>(weight);

    cudaFuncSetAttribute(deform_main, cudaFuncAttributeMaxDynamicSharedMemorySize,
                         SMEM_BYTES);
    deform_main<<<Bb * Hh, 384, SMEM_BYTES>>>(offset, bias, out);
}